// round 13
// baseline (speedup 1.0000x reference)
#include <cuda_runtime.h>
#include <math.h>
#include <stdint.h>

#define NN   256
#define TT   16383
#define BB   8
#define LL   2097152
#define FF   129
#define TILE 48
#define NTHR 256
#define NBLK ((TT + TILE - 1) / TILE)   // 342

#define NC    8                         // n-samples per chunk
#define NCH   (NN / NC)                 // 32 chunks
#define CROWS 144                       // coeff rows (129 real + padding)
#define SC_U2_PER_BUF (CROWS * (NC / 2))   // 576 ulonglong2 per buffer
#define SC_BYTES (2 * SC_U2_PER_BUF * 16)  // 18432

#define BFT ((size_t)BB * FF * TT)
#define BNT ((size_t)BB * NN * TT)
#define O_SPEC  ((size_t)0)
#define O_STFT  (BFT)
#define O_REAL  (BFT + BNT)
#define O_IMAG  (BFT + 2*BNT)
#define O_PHASE (BFT + 3*BNT)

__device__ __align__(16) float2 g_coeff[CROWS * NN];   // 294 KB

__device__ __forceinline__ unsigned long long pk2(float x, float y) {
    unsigned long long r;
    asm("mov.b64 %0, {%1,%2};" : "=l"(r) : "f"(x), "f"(y));
    return r;
}
__device__ __forceinline__ void upk2(unsigned long long v, float& x, float& y) {
    asm("mov.b64 {%0,%1}, %2;" : "=f"(x), "=f"(y) : "l"(v));
}
__device__ __forceinline__ void fma2(unsigned long long& d,
                                     unsigned long long a, unsigned long long b) {
    asm("fma.rn.f32x2 %0, %1, %2, %0;" : "+l"(d) : "l"(a), "l"(b));
}
__device__ __forceinline__ uint32_t smem_u32(const void* p) {
    uint32_t a;
    asm("{ .reg .u64 t; cvta.to.shared.u64 t, %1; cvt.u32.u64 %0, t; }"
        : "=r"(a) : "l"(p));
    return a;
}
__device__ __forceinline__ void cp_async16(uint32_t dst, const void* src) {
    asm volatile("cp.async.cg.shared.global [%0], [%1], 16;\n"
                 :: "r"(dst), "l"(src));
}

// Replica of reference coeff: exp((-2i*pi/256)*(f*n)); angle = fl32(c32*(f*n)),
// cos/sin via libdevice cosf/sinf (bit-identical to XLA:GPU's jnp.exp lowering).
__global__ void build_coeff() {
    int idx = blockIdx.x * 256 + threadIdx.x;
    if (idx >= CROWS * NN) return;
    int f = idx >> 8, n = idx & 255;
    const float c32 = (float)(-2.0 * M_PI / 256.0);
    float m  = (float)(f * n);
    float th = __fmul_rn(c32, m);
    g_coeff[idx] = make_float2(cosf(th), sinf(th));
}

__device__ __forceinline__ void issue_chunk(uint32_t sc_u32, int chunk, int tid) {
    int n0 = chunk * NC;
    uint32_t dbase = sc_u32 + (uint32_t)((chunk & 1) * SC_U2_PER_BUF) * 16;
    for (int j = tid; j < SC_U2_PER_BUF; j += NTHR) {
        int row = j >> 2, pair = j & 3;          // NC/2 = 4 u2 per row
        const float2* src = g_coeff + row * 256 + n0 + pair * 2;
        cp_async16(dbase + (uint32_t)j * 16, src);
    }
    asm volatile("cp.async.commit_group;" ::: "memory");
}

__global__ __launch_bounds__(NTHR, 3)
void dstft_main(const float* __restrict__ x,
                const float* __restrict__ wlp,
                const float* __restrict__ stp,
                const float* __restrict__ pwp,
                float* __restrict__ out)
{
    extern __shared__ __align__(16) char smraw[];
    ulonglong2* sc = (ulonglong2*)smraw;                 // [2][576]
    float* vt    = (float*)(smraw + SC_BYTES);           // [TILE][258]
    float* tsum  = vt + TILE * 258;
    float* sfrac = tsum + TILE;
    float* mcs   = sfrac + TILE;
    float* msn   = mcs + TILE;
    int*   sidx0 = (int*)(msn + TILE);

    const int tid = threadIdx.x;
    const int b   = blockIdx.y;
    const int t0  = blockIdx.x * TILE;

    const float wl = fminf(fmaxf(wlp[0], 12.8f), 256.0f);
    const float st = fminf(fmaxf(stp[0], 0.0f), 256.0f);
    const float p  = pwp[0];

    const uint32_t sc_u32 = smem_u32(sc);

    // Prefetch coeff chunk 0 immediately; overlaps with tap phases below.
    issue_chunk(sc_u32, 0, tid);

    if (tid < TILE) {
        int t = t0 + tid;
        float fv = __fmul_rn((float)t, st);   // == fp32 cumsum (exact here)
        float fl = floorf(fv);
        float fc = __fsub_rn(fv, fl);
        sfrac[tid] = fc;
        sidx0[tid] = (int)fl;
        float thm = __fmul_rn((float)(2.0 * M_PI / 256.0),
                              __fmul_rn(fc, 256.0f));
        mcs[tid] = cosf(thm);
        msn[tid] = sinf(thm);
    }
    __syncthreads();

    // ---- A1: hann taps (replica fp32 ops) ----
    {
        const float hi  = ceilf (__fdiv_rn(__fadd_rn(255.0f, wl), 2.0f));
        const float lo  = floorf(__fdiv_rn(__fsub_rn(255.0f, wl), 2.0f));
        const float off = __fdiv_rn(__fadd_rn(__fsub_rn(wl, 256.0f), 1.0f), 2.0f);
        const float twopi = (float)(2.0 * M_PI);
        for (int k = 0; k < TILE; ++k) {
            float base = __fsub_rn((float)tid, sfrac[k]);
            float arg  = __fdiv_rn(__fmul_rn(twopi, __fadd_rn(base, off)), wl);
            float tap  = __fsub_rn(0.5f, __fmul_rn(0.5f, cosf(arg)));
            if (base >= hi) tap = 0.0f;
            if (base <= lo) tap = 0.0f;
            vt[k * 258 + tid] = tap;
        }
    }
    __syncthreads();

    // ---- A2: per-frame tap sums (same per-frame order as R8-R12) ----
    {
        int w = tid >> 5, lane = tid & 31;
        for (int k0 = 0; k0 < TILE; k0 += 8) {
            int k = k0 + w;
            float s = 0.0f;
            #pragma unroll
            for (int j = 0; j < 256; j += 32) s += vt[k * 258 + j + lane];
            #pragma unroll
            for (int o = 16; o > 0; o >>= 1) s += __shfl_down_sync(0xffffffffu, s, o);
            if (lane == 0) tsum[k] = s;
        }
    }
    __syncthreads();

    // ---- A3: tapered = x_gather * (tap / sum) [^p] ----
    {
        const float* xb = x + (size_t)b * LL;
        for (int k = 0; k < TILE; ++k) {
            int t = t0 + k;
            float v = 0.0f;
            if (t < TT) {
                int gi = sidx0[k] + tid;
                float xv = (gi >= 0 && gi < LL) ? xb[gi] : 0.0f;
                float tapn = __fdiv_rn(vt[k * 258 + tid], tsum[k]);
                if (p != 1.0f) tapn = powf(tapn, p);
                v = __fmul_rn(xv, tapn);
            }
            vt[k * 258 + tid] = v;
        }
    }
    __syncthreads();

    // ---- B: chunked DFT; thread tile = 9 f-slots x 3 frames ----
    const int fr    = tid & 15;     // frames fr, fr+16, fr+32
    const int fslot = tid >> 4;     // f = fslot + 16i

    unsigned long long acc[27];
    #pragma unroll
    for (int i = 0; i < 27; ++i) acc[i] = 0ull;

    #pragma unroll 1
    for (int c = 0; c < NCH; ++c) {
        if (c + 1 < NCH) {
            issue_chunk(sc_u32, c + 1, tid);
            asm volatile("cp.async.wait_group 1;" ::: "memory");  // chunk c done
        } else {
            asm volatile("cp.async.wait_group 0;" ::: "memory");
        }
        __syncthreads();

        const ulonglong2* scp = sc + (c & 1) * SC_U2_PER_BUF;
        const int nbase = c * NC;
        #pragma unroll
        for (int np = 0; np < NC / 2; ++np) {
            int n = nbase + np * 2;
            float2 v0 = *(const float2*)&vt[fr * 258 + n];
            float2 v1 = *(const float2*)&vt[(fr + 16) * 258 + n];
            float2 v2 = *(const float2*)&vt[(fr + 32) * 258 + n];
            unsigned long long a00 = pk2(v0.x, v0.x);
            unsigned long long a01 = pk2(v0.y, v0.y);
            unsigned long long a10 = pk2(v1.x, v1.x);
            unsigned long long a11 = pk2(v1.y, v1.y);
            unsigned long long a20 = pk2(v2.x, v2.x);
            unsigned long long a21 = pk2(v2.y, v2.y);
            #pragma unroll
            for (int i = 0; i < 9; ++i) {
                ulonglong2 cc = scp[(fslot + 16 * i) * (NC / 2) + np];
                fma2(acc[i],      a00, cc.x);
                fma2(acc[i],      a01, cc.y);
                fma2(acc[9 + i],  a10, cc.x);
                fma2(acc[9 + i],  a11, cc.y);
                fma2(acc[18 + i], a20, cc.x);
                fma2(acc[18 + i], a21, cc.y);
            }
        }
        __syncthreads();   // compute on buffer done before it is refilled
    }

    // ---- C: sub-sample shift + outputs ----
    const float c2 = (float)(2.0 * M_PI / 256.0);
    #pragma unroll
    for (int i = 0; i < 9; ++i) {
        int f = fslot + 16 * i;
        if (f > 128) continue;
        #pragma unroll
        for (int j = 0; j < 3; ++j) {
            int frame = fr + 16 * j;
            int t = t0 + frame;
            if (t >= TT) continue;
            float Xr, Xi;
            upk2(acc[9 * j + i], Xr, Xi);

            float frac = sfrac[frame];
            float th = __fmul_rn(c2, __fmul_rn(frac, (float)f));
            float shc = cosf(th), shs = sinf(th);
            float Xr2 = __fsub_rn(__fmul_rn(Xr, shc), __fmul_rn(Xi, shs));
            float Xi2 = __fadd_rn(__fmul_rn(Xr, shs), __fmul_rn(Xi, shc));

            float spec = sqrtf(__fmaf_rn(Xr2, Xr2, __fmul_rn(Xi2, Xi2))) + 1.1920929e-7f;
            float ph   = atan2f(Xi2, Xr2);

            size_t ibf = ((size_t)b * FF + f) * TT + t;
            size_t ib  = ((size_t)b * NN + f) * TT + t;
            out[O_SPEC  + ibf] = spec;
            out[O_PHASE + ibf] = ph;
            out[O_STFT  + ib ] = Xr2;
            out[O_REAL  + ib ] = Xr2;
            out[O_IMAG  + ib ] = Xi2;

            if (f >= 1 && f <= 127) {
                float cp2 = mcs[frame], sp2 = msn[frame];
                float Xr3 = cp2 * Xr2 + sp2 * Xi2;   // e^{2pi i frac} * conj(X)
                float Xi3 = sp2 * Xr2 - cp2 * Xi2;
                size_t ib2 = ((size_t)b * NN + (NN - f)) * TT + t;
                out[O_STFT + ib2] = Xr3;
                out[O_REAL + ib2] = Xr3;
                out[O_IMAG + ib2] = Xi3;
            }
        }
    }
}

extern "C" void kernel_launch(void* const* d_in, const int* in_sizes, int n_in,
                              void* d_out, int out_size) {
    const float* x  = (const float*)d_in[0];
    const float* wl = (const float*)d_in[1];
    const float* st = (const float*)d_in[2];
    const float* pw = (const float*)d_in[3];
    float* out = (float*)d_out;

    build_coeff<<<(CROWS * NN + 255) / 256, 256>>>();

    const int smemBytes = SC_BYTES + (TILE * 258 + TILE * 5) * 4;   // ~69 KB
    static int attrSet = 0;
    if (!attrSet) {
        cudaFuncSetAttribute(dstft_main,
                             cudaFuncAttributeMaxDynamicSharedMemorySize,
                             smemBytes);
        attrSet = 1;
    }

    dim3 grid(NBLK, BB);
    dstft_main<<<grid, NTHR, smemBytes>>>(x, wl, st, pw, out);
}

// round 14
// speedup vs baseline: 1.2169x; 1.2169x over previous
#include <cuda_runtime.h>
#include <math.h>
#include <stdint.h>

#define NN   256
#define TT   16383
#define BB   8
#define LL   2097152
#define FF   129
#define TILE 32
#define NTHR 256
#define NBLK ((TT + TILE - 1) / TILE)   // 512

#define NC    8                         // n-samples per chunk
#define NCH   (NN / NC)                 // 32 chunks
#define CROWS 144                       // coeff rows (129 real + padding)
#define SC_U2_PER_BUF (CROWS * (NC / 2))   // 576 ulonglong2 per buffer
#define SC_BYTES (2 * SC_U2_PER_BUF * 16)  // 18432

#define BFT ((size_t)BB * FF * TT)
#define BNT ((size_t)BB * NN * TT)
#define O_SPEC  ((size_t)0)
#define O_STFT  (BFT)
#define O_REAL  (BFT + BNT)
#define O_IMAG  (BFT + 2*BNT)
#define O_PHASE (BFT + 3*BNT)

__device__ __align__(16) float2 g_coeff[CROWS * NN];   // 294 KB

__device__ __forceinline__ unsigned long long pk2(float x, float y) {
    unsigned long long r;
    asm("mov.b64 %0, {%1,%2};" : "=l"(r) : "f"(x), "f"(y));
    return r;
}
__device__ __forceinline__ void upk2(unsigned long long v, float& x, float& y) {
    asm("mov.b64 {%0,%1}, %2;" : "=f"(x), "=f"(y) : "l"(v));
}
__device__ __forceinline__ void fma2(unsigned long long& d,
                                     unsigned long long a, unsigned long long b) {
    asm("fma.rn.f32x2 %0, %1, %2, %0;" : "+l"(d) : "l"(a), "l"(b));
}
__device__ __forceinline__ uint32_t smem_u32(const void* p) {
    uint32_t a;
    asm("{ .reg .u64 t; cvta.to.shared.u64 t, %1; cvt.u32.u64 %0, t; }"
        : "=r"(a) : "l"(p));
    return a;
}
__device__ __forceinline__ void cp_async16(uint32_t dst, const void* src) {
    asm volatile("cp.async.cg.shared.global [%0], [%1], 16;\n"
                 :: "r"(dst), "l"(src));
}

// Replica of reference coeff: exp((-2i*pi/256)*(f*n)); angle = fl32(c32*(f*n)),
// cos/sin via libdevice cosf/sinf (bit-identical to XLA:GPU's jnp.exp lowering).
__global__ void build_coeff() {
    int idx = blockIdx.x * 256 + threadIdx.x;
    if (idx >= CROWS * NN) return;
    int f = idx >> 8, n = idx & 255;
    const float c32 = (float)(-2.0 * M_PI / 256.0);
    float m  = (float)(f * n);
    float th = __fmul_rn(c32, m);
    g_coeff[idx] = make_float2(cosf(th), sinf(th));
}

__device__ __forceinline__ void issue_chunk(uint32_t sc_u32, int chunk, int tid) {
    int n0 = chunk * NC;
    uint32_t dbase = sc_u32 + (uint32_t)((chunk & 1) * SC_U2_PER_BUF) * 16;
    for (int j = tid; j < SC_U2_PER_BUF; j += NTHR) {
        int row = j >> 2, pair = j & 3;          // NC/2 = 4 u2 per row
        const float2* src = g_coeff + row * 256 + n0 + pair * 2;
        cp_async16(dbase + (uint32_t)j * 16, src);
    }
    asm volatile("cp.async.commit_group;" ::: "memory");
}

__global__ __launch_bounds__(NTHR, 4)
void dstft_main(const float* __restrict__ x,
                const float* __restrict__ wlp,
                const float* __restrict__ stp,
                const float* __restrict__ pwp,
                float* __restrict__ out)
{
    extern __shared__ __align__(16) char smraw[];
    ulonglong2* sc = (ulonglong2*)smraw;                 // [2][576]
    float* vt    = (float*)(smraw + SC_BYTES);           // [TILE][258]
    float* tsum  = vt + TILE * 258;
    float* sfrac = tsum + TILE;
    float* mcs   = sfrac + TILE;
    float* msn   = mcs + TILE;
    int*   sidx0 = (int*)(msn + TILE);

    const int tid = threadIdx.x;
    const int b   = blockIdx.y;
    const int t0  = blockIdx.x * TILE;

    const float wl = fminf(fmaxf(wlp[0], 12.8f), 256.0f);
    const float st = fminf(fmaxf(stp[0], 0.0f), 256.0f);
    const float p  = pwp[0];

    const uint32_t sc_u32 = smem_u32(sc);

    // Prefetch coeff chunk 0 immediately; overlaps with tap phases below.
    issue_chunk(sc_u32, 0, tid);

    if (tid < TILE) {
        int t = t0 + tid;
        float fv = __fmul_rn((float)t, st);   // == fp32 cumsum (exact here)
        float fl = floorf(fv);
        float fc = __fsub_rn(fv, fl);
        sfrac[tid] = fc;
        sidx0[tid] = (int)fl;
        float thm = __fmul_rn((float)(2.0 * M_PI / 256.0),
                              __fmul_rn(fc, 256.0f));
        mcs[tid] = cosf(thm);
        msn[tid] = sinf(thm);
    }
    __syncthreads();

    // ---- A1: hann taps (replica fp32 ops) ----
    {
        const float hi  = ceilf (__fdiv_rn(__fadd_rn(255.0f, wl), 2.0f));
        const float lo  = floorf(__fdiv_rn(__fsub_rn(255.0f, wl), 2.0f));
        const float off = __fdiv_rn(__fadd_rn(__fsub_rn(wl, 256.0f), 1.0f), 2.0f);
        const float twopi = (float)(2.0 * M_PI);
        for (int k = 0; k < TILE; ++k) {
            float base = __fsub_rn((float)tid, sfrac[k]);
            float arg  = __fdiv_rn(__fmul_rn(twopi, __fadd_rn(base, off)), wl);
            float tap  = __fsub_rn(0.5f, __fmul_rn(0.5f, cosf(arg)));
            if (base >= hi) tap = 0.0f;
            if (base <= lo) tap = 0.0f;
            vt[k * 258 + tid] = tap;
        }
    }
    __syncthreads();

    // ---- A2: per-frame tap sums (same per-frame order as R8-R13) ----
    {
        int w = tid >> 5, lane = tid & 31;
        for (int k0 = 0; k0 < TILE; k0 += 8) {
            int k = k0 + w;
            float s = 0.0f;
            #pragma unroll
            for (int j = 0; j < 256; j += 32) s += vt[k * 258 + j + lane];
            #pragma unroll
            for (int o = 16; o > 0; o >>= 1) s += __shfl_down_sync(0xffffffffu, s, o);
            if (lane == 0) tsum[k] = s;
        }
    }
    __syncthreads();

    // ---- A3: tapered = x_gather * (tap / sum) [^p] ----
    {
        const float* xb = x + (size_t)b * LL;
        for (int k = 0; k < TILE; ++k) {
            int t = t0 + k;
            float v = 0.0f;
            if (t < TT) {
                int gi = sidx0[k] + tid;
                float xv = (gi >= 0 && gi < LL) ? xb[gi] : 0.0f;
                float tapn = __fdiv_rn(vt[k * 258 + tid], tsum[k]);
                if (p != 1.0f) tapn = powf(tapn, p);
                v = __fmul_rn(xv, tapn);
            }
            vt[k * 258 + tid] = v;
        }
    }
    __syncthreads();

    // ---- B: chunked DFT; thread tile = 9 f-slots x 2 frames ----
    const int fr    = tid & 15;     // frames fr, fr+16
    const int fslot = tid >> 4;     // f = fslot + 16i

    unsigned long long acc[18];
    #pragma unroll
    for (int i = 0; i < 18; ++i) acc[i] = 0ull;

    #pragma unroll 1
    for (int c = 0; c < NCH; ++c) {
        if (c + 1 < NCH) {
            issue_chunk(sc_u32, c + 1, tid);
            asm volatile("cp.async.wait_group 1;" ::: "memory");  // chunk c done
        } else {
            asm volatile("cp.async.wait_group 0;" ::: "memory");
        }
        __syncthreads();

        const ulonglong2* scp = sc + (c & 1) * SC_U2_PER_BUF;
        const int nbase = c * NC;
        #pragma unroll
        for (int np = 0; np < NC / 2; ++np) {
            int n = nbase + np * 2;
            float2 v0 = *(const float2*)&vt[fr * 258 + n];
            float2 v1 = *(const float2*)&vt[(fr + 16) * 258 + n];
            unsigned long long a00 = pk2(v0.x, v0.x);
            unsigned long long a01 = pk2(v0.y, v0.y);
            unsigned long long a10 = pk2(v1.x, v1.x);
            unsigned long long a11 = pk2(v1.y, v1.y);
            #pragma unroll
            for (int i = 0; i < 9; ++i) {
                ulonglong2 cc = scp[(fslot + 16 * i) * (NC / 2) + np];
                fma2(acc[i],     a00, cc.x);
                fma2(acc[i],     a01, cc.y);
                fma2(acc[9 + i], a10, cc.x);
                fma2(acc[9 + i], a11, cc.y);
            }
        }
        __syncthreads();   // compute on buffer done before it is refilled
    }

    // ---- C: sub-sample shift + outputs ----
    const float c2 = (float)(2.0 * M_PI / 256.0);
    #pragma unroll
    for (int i = 0; i < 9; ++i) {
        int f = fslot + 16 * i;
        if (f > 128) continue;
        #pragma unroll
        for (int j = 0; j < 2; ++j) {
            int frame = fr + 16 * j;
            int t = t0 + frame;
            if (t >= TT) continue;
            float Xr, Xi;
            upk2(acc[9 * j + i], Xr, Xi);

            float frac = sfrac[frame];
            float th = __fmul_rn(c2, __fmul_rn(frac, (float)f));
            float shc = cosf(th), shs = sinf(th);
            float Xr2 = __fsub_rn(__fmul_rn(Xr, shc), __fmul_rn(Xi, shs));
            float Xi2 = __fadd_rn(__fmul_rn(Xr, shs), __fmul_rn(Xi, shc));

            float spec = sqrtf(__fmaf_rn(Xr2, Xr2, __fmul_rn(Xi2, Xi2))) + 1.1920929e-7f;
            float ph   = atan2f(Xi2, Xr2);

            size_t ibf = ((size_t)b * FF + f) * TT + t;
            size_t ib  = ((size_t)b * NN + f) * TT + t;
            out[O_SPEC  + ibf] = spec;
            out[O_PHASE + ibf] = ph;
            out[O_STFT  + ib ] = Xr2;
            out[O_REAL  + ib ] = Xr2;
            out[O_IMAG  + ib ] = Xi2;

            if (f >= 1 && f <= 127) {
                float cp2 = mcs[frame], sp2 = msn[frame];
                float Xr3 = cp2 * Xr2 + sp2 * Xi2;   // e^{2pi i frac} * conj(X)
                float Xi3 = sp2 * Xr2 - cp2 * Xi2;
                size_t ib2 = ((size_t)b * NN + (NN - f)) * TT + t;
                out[O_STFT + ib2] = Xr3;
                out[O_REAL + ib2] = Xr3;
                out[O_IMAG + ib2] = Xi3;
            }
        }
    }
}

extern "C" void kernel_launch(void* const* d_in, const int* in_sizes, int n_in,
                              void* d_out, int out_size) {
    const float* x  = (const float*)d_in[0];
    const float* wl = (const float*)d_in[1];
    const float* st = (const float*)d_in[2];
    const float* pw = (const float*)d_in[3];
    float* out = (float*)d_out;

    build_coeff<<<(CROWS * NN + 255) / 256, 256>>>();

    const int smemBytes = SC_BYTES + (TILE * 258 + TILE * 5) * 4;   // ~51 KB
    static int attrSet = 0;
    if (!attrSet) {
        cudaFuncSetAttribute(dstft_main,
                             cudaFuncAttributeMaxDynamicSharedMemorySize,
                             smemBytes);
        attrSet = 1;
    }

    dim3 grid(NBLK, BB);
    dstft_main<<<grid, NTHR, smemBytes>>>(x, wl, st, pw, out);
}

// round 15
// speedup vs baseline: 1.2561x; 1.0322x over previous
#include <cuda_runtime.h>
#include <math.h>
#include <stdint.h>

#define NN   256
#define TT   16383
#define BB   8
#define LL   2097152
#define FF   129
#define TILE 32
#define NTHR 256
#define NBLK ((TT + TILE - 1) / TILE)   // 512

#define NC    8                         // n-samples per chunk
#define NCH   (NN / NC)                 // 32 chunks
#define CROWS 144                       // global coeff rows (129 used)
#define SROWS 129                       // staged rows per chunk (no padding)
#define SC_U2_PER_BUF (SROWS * (NC / 2))   // 516 ulonglong2 per buffer
#define SC_BYTES (2 * SC_U2_PER_BUF * 16)  // 16512

#define BFT ((size_t)BB * FF * TT)
#define BNT ((size_t)BB * NN * TT)
#define O_SPEC  ((size_t)0)
#define O_STFT  (BFT)
#define O_REAL  (BFT + BNT)
#define O_IMAG  (BFT + 2*BNT)
#define O_PHASE (BFT + 3*BNT)

__device__ __align__(16) float2 g_coeff[CROWS * NN];   // 294 KB
__device__ float g_tap[(size_t)TT * NN];               // 16.8 MB (normalized taps)

__device__ __forceinline__ unsigned long long pk2(float x, float y) {
    unsigned long long r;
    asm("mov.b64 %0, {%1,%2};" : "=l"(r) : "f"(x), "f"(y));
    return r;
}
__device__ __forceinline__ void upk2(unsigned long long v, float& x, float& y) {
    asm("mov.b64 {%0,%1}, %2;" : "=f"(x), "=f"(y) : "l"(v));
}
__device__ __forceinline__ void fma2(unsigned long long& d,
                                     unsigned long long a, unsigned long long b) {
    asm("fma.rn.f32x2 %0, %1, %2, %0;" : "+l"(d) : "l"(a), "l"(b));
}
__device__ __forceinline__ uint32_t smem_u32(const void* p) {
    uint32_t a;
    asm("{ .reg .u64 t; cvta.to.shared.u64 t, %1; cvt.u32.u64 %0, t; }"
        : "=r"(a) : "l"(p));
    return a;
}
__device__ __forceinline__ void cp_async16(uint32_t dst, const void* src) {
    asm volatile("cp.async.cg.shared.global [%0], [%1], 16;\n"
                 :: "r"(dst), "l"(src));
}

// Replica coeff: exp((-2i*pi/256)*(f*n)); angle = fl32(c32*(f*n)); libdevice cosf/sinf.
__global__ void build_coeff() {
    int idx = blockIdx.x * 256 + threadIdx.x;
    if (idx >= CROWS * NN) return;
    int f = idx >> 8, n = idx & 255;
    const float c32 = (float)(-2.0 * M_PI / 256.0);
    float m  = (float)(f * n);
    float th = __fmul_rn(c32, m);
    g_coeff[idx] = make_float2(cosf(th), sinf(th));
}

// Replica taps: identical fp32 ops + identical reduction order as the fused A1/A2
// phases of previous rounds (lane strided sum + shfl butterfly), then div/pow.
__global__ __launch_bounds__(256)
void build_taps(const float* __restrict__ wlp,
                const float* __restrict__ stp,
                const float* __restrict__ pwp)
{
    __shared__ float tp[256];
    __shared__ float ssum;
    const int n = threadIdx.x;
    const int t = blockIdx.x;

    const float wl = fminf(fmaxf(wlp[0], 12.8f), 256.0f);
    const float st = fminf(fmaxf(stp[0], 0.0f), 256.0f);
    const float p  = pwp[0];

    float fv = __fmul_rn((float)t, st);
    float frac = __fsub_rn(fv, floorf(fv));

    const float hi  = ceilf (__fdiv_rn(__fadd_rn(255.0f, wl), 2.0f));
    const float lo  = floorf(__fdiv_rn(__fsub_rn(255.0f, wl), 2.0f));
    const float off = __fdiv_rn(__fadd_rn(__fsub_rn(wl, 256.0f), 1.0f), 2.0f);
    const float twopi = (float)(2.0 * M_PI);

    float base = __fsub_rn((float)n, frac);
    float arg  = __fdiv_rn(__fmul_rn(twopi, __fadd_rn(base, off)), wl);
    float tap  = __fsub_rn(0.5f, __fmul_rn(0.5f, cosf(arg)));
    if (base >= hi) tap = 0.0f;
    if (base <= lo) tap = 0.0f;
    tp[n] = tap;
    __syncthreads();

    if (n < 32) {
        float s = 0.0f;
        #pragma unroll
        for (int j = 0; j < 256; j += 32) s += tp[j + n];
        #pragma unroll
        for (int o = 16; o > 0; o >>= 1) s += __shfl_down_sync(0xffffffffu, s, o);
        if (n == 0) ssum = s;
    }
    __syncthreads();

    float tapn = __fdiv_rn(tap, ssum);
    if (p != 1.0f) tapn = powf(tapn, p);
    g_tap[(size_t)t * NN + n] = tapn;
}

__device__ __forceinline__ void issue_chunk(uint32_t sc_u32, int chunk, int tid) {
    int n0 = chunk * NC;
    uint32_t dbase = sc_u32 + (uint32_t)((chunk & 1) * SC_U2_PER_BUF) * 16;
    for (int j = tid; j < SC_U2_PER_BUF; j += NTHR) {
        int row = j >> 2, pair = j & 3;          // NC/2 = 4 u2 per row
        const float2* src = g_coeff + row * 256 + n0 + pair * 2;
        cp_async16(dbase + (uint32_t)j * 16, src);
    }
    asm volatile("cp.async.commit_group;" ::: "memory");
}

__global__ __launch_bounds__(NTHR, 4)
void dstft_main(const float* __restrict__ x,
                const float* __restrict__ stp,
                float* __restrict__ out)
{
    extern __shared__ __align__(16) char smraw[];
    ulonglong2* sc = (ulonglong2*)smraw;                 // [2][516]
    float* vt    = (float*)(smraw + SC_BYTES);           // [TILE][258]
    float* sfrac = vt + TILE * 258;
    float* mcs   = sfrac + TILE;
    float* msn   = mcs + TILE;
    int*   sidx0 = (int*)(msn + TILE);

    const int tid = threadIdx.x;
    const int b   = blockIdx.y;
    const int t0  = blockIdx.x * TILE;

    const float st = fminf(fmaxf(stp[0], 0.0f), 256.0f);
    const uint32_t sc_u32 = smem_u32(sc);

    // Prefetch coeff chunk 0; overlaps with the gather phase below.
    issue_chunk(sc_u32, 0, tid);

    if (tid < TILE) {
        int t = t0 + tid;
        float fv = __fmul_rn((float)t, st);   // == fp32 cumsum (exact here)
        float fl = floorf(fv);
        float fc = __fsub_rn(fv, fl);
        sfrac[tid] = fc;
        sidx0[tid] = (int)fl;
        float thm = __fmul_rn((float)(2.0 * M_PI / 256.0),
                              __fmul_rn(fc, 256.0f));
        mcs[tid] = cosf(thm);
        msn[tid] = sinf(thm);
    }
    __syncthreads();

    // ---- A: tapered = x_gather * tap_norm (precomputed) ----
    {
        const float* xb = x + (size_t)b * LL;
        for (int k = 0; k < TILE; ++k) {
            int t = t0 + k;
            float v = 0.0f;
            if (t < TT) {
                int gi = sidx0[k] + tid;
                float xv = (gi >= 0 && gi < LL) ? xb[gi] : 0.0f;
                float tapn = __ldg(&g_tap[(size_t)t * NN + tid]);
                v = __fmul_rn(xv, tapn);
            }
            vt[k * 258 + tid] = v;
        }
    }
    __syncthreads();

    // ---- B: chunked DFT; thread tile = 8 f-slots x 2 frames (+f=128 on fslot 15) ----
    const int fr    = tid & 15;     // frames fr, fr+16
    const int fslot = tid >> 4;     // f = fslot + 16i, i<8
    const bool has128 = (fslot == 15);

    unsigned long long acc[18];
    #pragma unroll
    for (int i = 0; i < 18; ++i) acc[i] = 0ull;

    #pragma unroll 1
    for (int c = 0; c < NCH; ++c) {
        if (c + 1 < NCH) {
            issue_chunk(sc_u32, c + 1, tid);
            asm volatile("cp.async.wait_group 1;" ::: "memory");
        } else {
            asm volatile("cp.async.wait_group 0;" ::: "memory");
        }
        __syncthreads();

        const ulonglong2* scp = sc + (c & 1) * SC_U2_PER_BUF;
        const int nbase = c * NC;
        #pragma unroll
        for (int np = 0; np < NC / 2; ++np) {
            int n = nbase + np * 2;
            float2 v0 = *(const float2*)&vt[fr * 258 + n];
            float2 v1 = *(const float2*)&vt[(fr + 16) * 258 + n];
            unsigned long long a00 = pk2(v0.x, v0.x);
            unsigned long long a01 = pk2(v0.y, v0.y);
            unsigned long long a10 = pk2(v1.x, v1.x);
            unsigned long long a11 = pk2(v1.y, v1.y);
            #pragma unroll
            for (int i = 0; i < 8; ++i) {
                ulonglong2 cc = scp[(fslot + 16 * i) * (NC / 2) + np];
                fma2(acc[i],     a00, cc.x);
                fma2(acc[i],     a01, cc.y);
                fma2(acc[8 + i], a10, cc.x);
                fma2(acc[8 + i], a11, cc.y);
            }
            if (has128) {
                ulonglong2 cc = scp[128 * (NC / 2) + np];
                fma2(acc[16], a00, cc.x);
                fma2(acc[16], a01, cc.y);
                fma2(acc[17], a10, cc.x);
                fma2(acc[17], a11, cc.y);
            }
        }
        __syncthreads();
    }

    // ---- C: sub-sample shift + outputs ----
    const float c2 = (float)(2.0 * M_PI / 256.0);
    #pragma unroll
    for (int i = 0; i < 9; ++i) {
        int f;
        if (i < 8) f = fslot + 16 * i;
        else { if (!has128) continue; f = 128; }
        #pragma unroll
        for (int j = 0; j < 2; ++j) {
            int frame = fr + 16 * j;
            int t = t0 + frame;
            if (t >= TT) continue;
            float Xr, Xi;
            upk2(acc[(i < 8) ? (8 * j + i) : (16 + j)], Xr, Xi);

            float frac = sfrac[frame];
            float th = __fmul_rn(c2, __fmul_rn(frac, (float)f));
            float shc = cosf(th), shs = sinf(th);
            float Xr2 = __fsub_rn(__fmul_rn(Xr, shc), __fmul_rn(Xi, shs));
            float Xi2 = __fadd_rn(__fmul_rn(Xr, shs), __fmul_rn(Xi, shc));

            float spec = sqrtf(__fmaf_rn(Xr2, Xr2, __fmul_rn(Xi2, Xi2))) + 1.1920929e-7f;
            float ph   = atan2f(Xi2, Xr2);

            size_t ibf = ((size_t)b * FF + f) * TT + t;
            size_t ib  = ((size_t)b * NN + f) * TT + t;
            out[O_SPEC  + ibf] = spec;
            out[O_PHASE + ibf] = ph;
            out[O_STFT  + ib ] = Xr2;
            out[O_REAL  + ib ] = Xr2;
            out[O_IMAG  + ib ] = Xi2;

            if (f >= 1 && f <= 127) {
                float cp2 = mcs[frame], sp2 = msn[frame];
                float Xr3 = cp2 * Xr2 + sp2 * Xi2;   // e^{2pi i frac} * conj(X)
                float Xi3 = sp2 * Xr2 - cp2 * Xi2;
                size_t ib2 = ((size_t)b * NN + (NN - f)) * TT + t;
                out[O_STFT + ib2] = Xr3;
                out[O_REAL + ib2] = Xr3;
                out[O_IMAG + ib2] = Xi3;
            }
        }
    }
}

extern "C" void kernel_launch(void* const* d_in, const int* in_sizes, int n_in,
                              void* d_out, int out_size) {
    const float* x  = (const float*)d_in[0];
    const float* wl = (const float*)d_in[1];
    const float* st = (const float*)d_in[2];
    const float* pw = (const float*)d_in[3];
    float* out = (float*)d_out;

    build_coeff<<<(CROWS * NN + 255) / 256, 256>>>();
    build_taps<<<TT, 256>>>(wl, st, pw);

    const int smemBytes = SC_BYTES + (TILE * 258 + TILE * 4) * 4;   // ~49.6 KB
    static int attrSet = 0;
    if (!attrSet) {
        cudaFuncSetAttribute(dstft_main,
                             cudaFuncAttributeMaxDynamicSharedMemorySize,
                             smemBytes);
        attrSet = 1;
    }

    dim3 grid(NBLK, BB);
    dstft_main<<<grid, NTHR, smemBytes>>>(x, st, out);
}

// round 16
// speedup vs baseline: 1.3125x; 1.0449x over previous
#include <cuda_runtime.h>
#include <math.h>
#include <stdint.h>

#define NN   256
#define TT   16383
#define BB   8
#define LL   2097152
#define FF   129
#define TILE 32
#define NTHR 256
#define NBLK ((TT + TILE - 1) / TILE)   // 512

#define NC    8                         // n-samples per chunk
#define NCH   (NN / NC)                 // 32 chunks
#define CROWS 144                       // global coeff rows (129 used)
#define WROWS 17                        // rows staged per warp (16 + f=128)
#define W_U2  (WROWS * (NC / 2))        // 68 ulonglong2 per warp buffer
#define WSC_BYTES (8 * 2 * W_U2 * 16)   // 17408

#define BFT ((size_t)BB * FF * TT)
#define BNT ((size_t)BB * NN * TT)
#define O_SPEC  ((size_t)0)
#define O_STFT  (BFT)
#define O_REAL  (BFT + BNT)
#define O_IMAG  (BFT + 2*BNT)
#define O_PHASE (BFT + 3*BNT)

__device__ __align__(16) float2 g_coeff[CROWS * NN];   // 294 KB
__device__ float g_tap[(size_t)TT * NN];               // 16.8 MB (normalized taps)

__device__ __forceinline__ unsigned long long pk2(float x, float y) {
    unsigned long long r;
    asm("mov.b64 %0, {%1,%2};" : "=l"(r) : "f"(x), "f"(y));
    return r;
}
__device__ __forceinline__ void upk2(unsigned long long v, float& x, float& y) {
    asm("mov.b64 {%0,%1}, %2;" : "=f"(x), "=f"(y) : "l"(v));
}
__device__ __forceinline__ void fma2(unsigned long long& d,
                                     unsigned long long a, unsigned long long b) {
    asm("fma.rn.f32x2 %0, %1, %2, %0;" : "+l"(d) : "l"(a), "l"(b));
}
__device__ __forceinline__ uint32_t smem_u32(const void* p) {
    uint32_t a;
    asm("{ .reg .u64 t; cvta.to.shared.u64 t, %1; cvt.u32.u64 %0, t; }"
        : "=r"(a) : "l"(p));
    return a;
}
__device__ __forceinline__ void cp_async16(uint32_t dst, const void* src) {
    asm volatile("cp.async.cg.shared.global [%0], [%1], 16;\n"
                 :: "r"(dst), "l"(src));
}

// Replica coeff: exp((-2i*pi/256)*(f*n)); angle = fl32(c32*(f*n)); libdevice cosf/sinf.
__global__ void build_coeff() {
    int idx = blockIdx.x * 256 + threadIdx.x;
    if (idx >= CROWS * NN) return;
    int f = idx >> 8, n = idx & 255;
    const float c32 = (float)(-2.0 * M_PI / 256.0);
    float m  = (float)(f * n);
    float th = __fmul_rn(c32, m);
    g_coeff[idx] = make_float2(cosf(th), sinf(th));
}

// Replica taps: identical fp32 ops + identical reduction order as earlier rounds.
__global__ __launch_bounds__(256)
void build_taps(const float* __restrict__ wlp,
                const float* __restrict__ stp,
                const float* __restrict__ pwp)
{
    __shared__ float tp[256];
    __shared__ float ssum;
    const int n = threadIdx.x;
    const int t = blockIdx.x;

    const float wl = fminf(fmaxf(wlp[0], 12.8f), 256.0f);
    const float st = fminf(fmaxf(stp[0], 0.0f), 256.0f);
    const float p  = pwp[0];

    float fv = __fmul_rn((float)t, st);
    float frac = __fsub_rn(fv, floorf(fv));

    const float hi  = ceilf (__fdiv_rn(__fadd_rn(255.0f, wl), 2.0f));
    const float lo  = floorf(__fdiv_rn(__fsub_rn(255.0f, wl), 2.0f));
    const float off = __fdiv_rn(__fadd_rn(__fsub_rn(wl, 256.0f), 1.0f), 2.0f);
    const float twopi = (float)(2.0 * M_PI);

    float base = __fsub_rn((float)n, frac);
    float arg  = __fdiv_rn(__fmul_rn(twopi, __fadd_rn(base, off)), wl);
    float tap  = __fsub_rn(0.5f, __fmul_rn(0.5f, cosf(arg)));
    if (base >= hi) tap = 0.0f;
    if (base <= lo) tap = 0.0f;
    tp[n] = tap;
    __syncthreads();

    if (n < 32) {
        float s = 0.0f;
        #pragma unroll
        for (int j = 0; j < 256; j += 32) s += tp[j + n];
        #pragma unroll
        for (int o = 16; o > 0; o >>= 1) s += __shfl_down_sync(0xffffffffu, s, o);
        if (n == 0) ssum = s;
    }
    __syncthreads();

    float tapn = __fdiv_rn(tap, ssum);
    if (p != 1.0f) tapn = powf(tapn, p);
    g_tap[(size_t)t * NN + n] = tapn;
}

// Row k (0..16) of warp w's staging tile.
__device__ __forceinline__ int wrow(int w, int k) {
    if (k < 8)  return 2 * w + 16 * k;
    if (k < 16) return 2 * w + 1 + 16 * (k - 8);
    return 128;
}

// Warp-private coeff chunk staging: each lane moves <=3 of the 68 16B items.
__device__ __forceinline__ void warp_stage(uint32_t wbase_u32, int chunk,
                                           int w, int lane) {
    int n0 = chunk * NC;
    uint32_t dbase = wbase_u32 + (uint32_t)((chunk & 1) * W_U2) * 16;
    #pragma unroll
    for (int j0 = 0; j0 < W_U2; j0 += 32) {
        int j = j0 + lane;
        if (j < W_U2) {
            int k = j >> 2, pair = j & 3;
            const float2* src = g_coeff + wrow(w, k) * 256 + n0 + pair * 2;
            cp_async16(dbase + (uint32_t)j * 16, src);
        }
    }
    asm volatile("cp.async.commit_group;" ::: "memory");
}

__global__ __launch_bounds__(NTHR, 4)
void dstft_main(const float* __restrict__ x,
                const float* __restrict__ stp,
                float* __restrict__ out)
{
    extern __shared__ __align__(16) char smraw[];
    ulonglong2* wsc = (ulonglong2*)smraw;                // [8][2][68]
    float* vt    = (float*)(smraw + WSC_BYTES);          // [TILE][258]
    float* sfrac = vt + TILE * 258;
    float* mcs   = sfrac + TILE;
    float* msn   = mcs + TILE;
    int*   sidx0 = (int*)(msn + TILE);

    const int tid  = threadIdx.x;
    const int w    = tid >> 5;
    const int lane = tid & 31;
    const int b    = blockIdx.y;
    const int t0   = blockIdx.x * TILE;

    const float st = fminf(fmaxf(stp[0], 0.0f), 256.0f);
    const uint32_t wbase_u32 = smem_u32(wsc) + (uint32_t)(w * 2 * W_U2) * 16;

    // Stage chunk 0 immediately (warp-private; overlaps gather below).
    warp_stage(wbase_u32, 0, w, lane);

    if (tid < TILE) {
        int t = t0 + tid;
        float fv = __fmul_rn((float)t, st);   // == fp32 cumsum (exact here)
        float fl = floorf(fv);
        float fc = __fsub_rn(fv, fl);
        sfrac[tid] = fc;
        sidx0[tid] = (int)fl;
        float thm = __fmul_rn((float)(2.0 * M_PI / 256.0),
                              __fmul_rn(fc, 256.0f));
        mcs[tid] = cosf(thm);
        msn[tid] = sinf(thm);
    }
    __syncthreads();

    // ---- A: tapered = x_gather * tap_norm (precomputed) ----
    {
        const float* xb = x + (size_t)b * LL;
        for (int k = 0; k < TILE; ++k) {
            int t = t0 + k;
            float v = 0.0f;
            if (t < TT) {
                int gi = sidx0[k] + tid;
                float xv = (gi >= 0 && gi < LL) ? xb[gi] : 0.0f;
                float tapn = __ldg(&g_tap[(size_t)t * NN + tid]);
                v = __fmul_rn(xv, tapn);
            }
            vt[k * 258 + tid] = v;
        }
    }
    __syncthreads();   // vt visible to all warps; last block-wide barrier

    // ---- B: chunked DFT, warp-private double-buffered coeffs, barrier-free ----
    const int fr    = tid & 15;          // frames fr, fr+16
    const int fslot = tid >> 4;          // f = fslot + 16i, i<8
    const int half  = (lane >= 16);      // which fslot this half-warp owns
    const bool has128 = (fslot == 15);   // warp 7, lanes 16-31

    unsigned long long acc[18];
    #pragma unroll
    for (int i = 0; i < 18; ++i) acc[i] = 0ull;

    const ulonglong2* wp0 = wsc + w * 2 * W_U2;

    #pragma unroll 1
    for (int c = 0; c < NCH; ++c) {
        if (c + 1 < NCH) {
            warp_stage(wbase_u32, c + 1, w, lane);
            asm volatile("cp.async.wait_group 1;" ::: "memory");  // chunk c done
        } else {
            asm volatile("cp.async.wait_group 0;" ::: "memory");
        }
        __syncwarp();

        const ulonglong2* wp = wp0 + (c & 1) * W_U2;
        const int nbase = c * NC;
        #pragma unroll
        for (int np = 0; np < NC / 2; ++np) {
            int n = nbase + np * 2;
            float2 v0 = *(const float2*)&vt[fr * 258 + n];
            float2 v1 = *(const float2*)&vt[(fr + 16) * 258 + n];
            unsigned long long a00 = pk2(v0.x, v0.x);
            unsigned long long a01 = pk2(v0.y, v0.y);
            unsigned long long a10 = pk2(v1.x, v1.x);
            unsigned long long a11 = pk2(v1.y, v1.y);
            #pragma unroll
            for (int i = 0; i < 8; ++i) {
                // row k = half*8 + i of this warp's tile
                ulonglong2 cc = wp[(half * 8 + i) * (NC / 2) + np];
                fma2(acc[i],     a00, cc.x);
                fma2(acc[i],     a01, cc.y);
                fma2(acc[8 + i], a10, cc.x);
                fma2(acc[8 + i], a11, cc.y);
            }
            if (has128) {
                ulonglong2 cc = wp[16 * (NC / 2) + np];   // row 16 = f 128
                fma2(acc[16], a00, cc.x);
                fma2(acc[16], a01, cc.y);
                fma2(acc[17], a10, cc.x);
                fma2(acc[17], a11, cc.y);
            }
        }
        __syncwarp();   // all lanes done with buffer before warp restages it
    }

    // ---- C: sub-sample shift + outputs ----
    const float c2 = (float)(2.0 * M_PI / 256.0);
    #pragma unroll
    for (int i = 0; i < 9; ++i) {
        int f;
        if (i < 8) f = fslot + 16 * i;
        else { if (!has128) continue; f = 128; }
        #pragma unroll
        for (int j = 0; j < 2; ++j) {
            int frame = fr + 16 * j;
            int t = t0 + frame;
            if (t >= TT) continue;
            float Xr, Xi;
            upk2(acc[(i < 8) ? (8 * j + i) : (16 + j)], Xr, Xi);

            float frac = sfrac[frame];
            float th = __fmul_rn(c2, __fmul_rn(frac, (float)f));
            float shc = cosf(th), shs = sinf(th);
            float Xr2 = __fsub_rn(__fmul_rn(Xr, shc), __fmul_rn(Xi, shs));
            float Xi2 = __fadd_rn(__fmul_rn(Xr, shs), __fmul_rn(Xi, shc));

            float spec = sqrtf(__fmaf_rn(Xr2, Xr2, __fmul_rn(Xi2, Xi2))) + 1.1920929e-7f;
            float ph   = atan2f(Xi2, Xr2);

            size_t ibf = ((size_t)b * FF + f) * TT + t;
            size_t ib  = ((size_t)b * NN + f) * TT + t;
            out[O_SPEC  + ibf] = spec;
            out[O_PHASE + ibf] = ph;
            out[O_STFT  + ib ] = Xr2;
            out[O_REAL  + ib ] = Xr2;
            out[O_IMAG  + ib ] = Xi2;

            if (f >= 1 && f <= 127) {
                float cp2 = mcs[frame], sp2 = msn[frame];
                float Xr3 = cp2 * Xr2 + sp2 * Xi2;   // e^{2pi i frac} * conj(X)
                float Xi3 = sp2 * Xr2 - cp2 * Xi2;
                size_t ib2 = ((size_t)b * NN + (NN - f)) * TT + t;
                out[O_STFT + ib2] = Xr3;
                out[O_REAL + ib2] = Xr3;
                out[O_IMAG + ib2] = Xi3;
            }
        }
    }
}

extern "C" void kernel_launch(void* const* d_in, const int* in_sizes, int n_in,
                              void* d_out, int out_size) {
    const float* x  = (const float*)d_in[0];
    const float* wl = (const float*)d_in[1];
    const float* st = (const float*)d_in[2];
    const float* pw = (const float*)d_in[3];
    float* out = (float*)d_out;

    build_coeff<<<(CROWS * NN + 255) / 256, 256>>>();
    build_taps<<<TT, 256>>>(wl, st, pw);

    const int smemBytes = WSC_BYTES + (TILE * 258 + TILE * 4) * 4;   // ~50.6 KB
    static int attrSet = 0;
    if (!attrSet) {
        cudaFuncSetAttribute(dstft_main,
                             cudaFuncAttributeMaxDynamicSharedMemorySize,
                             smemBytes);
        attrSet = 1;
    }

    dim3 grid(NBLK, BB);
    dstft_main<<<grid, NTHR, smemBytes>>>(x, st, out);
}